// round 14
// baseline (speedup 1.0000x reference)
#include <cuda_runtime.h>
#include <cuda_bf16.h>
#include <cuda_fp16.h>
#include <cstdint>

#define LDIM 768
#define LL   (768*768)
#define FDIM 128
#define PDIM 32

// ---------------- device scratch (allocation-free rule) ----------------
__device__ __nv_bfloat16 g_Wbh[192*128];            // reordered weights hi [n][k]
__device__ __nv_bfloat16 g_Wbl[192*128];            // reordered weights lo [n][k]
__device__ __nv_bfloat16 g_projh[(size_t)PDIM*LL];  // proj hi, channel-major [c][pos]
__device__ __nv_bfloat16 g_projl[(size_t)PDIM*LL];  // proj lo
__device__ float         g_pair[(size_t)PDIM*LL];   // pair, channel-major [c][i*L+j]
__device__ __half        g_gate16[(size_t)LL*FDIM]; // gate fp16 [pos][f]

// precise sigmoid (proj path: feeds LN-amplified einsum)
__device__ __forceinline__ float sigmoidf_(float x) { return 1.0f/(1.0f + __expf(-x)); }

__device__ __forceinline__ void ldsm4(uint32_t (&r)[4], uint32_t addr) {
    asm volatile("ldmatrix.sync.aligned.m8n8.x4.shared.b16 {%0,%1,%2,%3}, [%4];"
        : "=r"(r[0]), "=r"(r[1]), "=r"(r[2]), "=r"(r[3]) : "r"(addr));
}
__device__ __forceinline__ void mma_bf16(float (&c)[4], const uint32_t (&a)[4],
                                         uint32_t b0, uint32_t b1) {
    asm volatile("mma.sync.aligned.m16n8k16.row.col.f32.bf16.bf16.f32 "
        "{%0,%1,%2,%3},{%4,%5,%6,%7},{%8,%9},{%0,%1,%2,%3};"
        : "+f"(c[0]), "+f"(c[1]), "+f"(c[2]), "+f"(c[3])
        : "r"(a[0]), "r"(a[1]), "r"(a[2]), "r"(a[3]), "r"(b0), "r"(b1));
}
__device__ __forceinline__ uint32_t smaddr(const void* p) {
    return (uint32_t)__cvta_generic_to_shared(p);
}
__device__ __forceinline__ void cpasync16(uint32_t dst, const void* src) {
    asm volatile("cp.async.cg.shared.global [%0], [%1], 16;" :: "r"(dst), "l"(src));
}
#define CP_COMMIT()  asm volatile("cp.async.commit_group;")
#define CP_WAIT(n)   asm volatile("cp.async.wait_group %0;" :: "n"(n))

// packed fp16 sigmoid: sigma(z) = 0.5*tanh(z/2)+0.5, two lanes per MUFU
__device__ __forceinline__ __half2 sigmoid2_h2(__half2 z) {
    const __half2 h05 = __float2half2_rn(0.5f);
    __half2 zh = __hmul2(z, h05);
    uint32_t tt;
    asm("tanh.approx.f16x2 %0, %1;" : "=r"(tt) : "r"(*(uint32_t*)&zh));
    return __hfma2(*(__half2*)&tt, h05, h05);
}

// ---------------------------------------------------------------------------
// Kernel 0: pack weights -> bf16 hi/lo planes, [n][k] layout.
// ---------------------------------------------------------------------------
__global__ void k_pack(const float* __restrict__ aW, const float* __restrict__ agW,
                       const float* __restrict__ gW)
{
    int idx = blockIdx.x * 256 + threadIdx.x;
    if (idx >= 192*128) return;
    int n = idx >> 7, k = idx & 127;
    float v;
    if (n < 64) { int ch = n >> 1; v = (n & 1) ? agW[ch*FDIM + k] : aW[ch*FDIM + k]; }
    else        { v = gW[(n-64)*FDIM + k]; }
    __nv_bfloat16 vh = __float2bfloat16(v);
    __nv_bfloat16 vl = __float2bfloat16(v - __bfloat162float(vh));
    g_Wbh[idx] = vh;
    g_Wbl[idx] = vl;
}

// ---------------------------------------------------------------------------
// Kernel 1: LN(F) + X[128,128] @ Wcat[128,192] via bf16 tensor MMA.
// 512 threads = 16 warps; warp tile 32x48. SMSP-balanced mapping.
// proj cols (<64): 3 terms + precise sigmoid; gate cols: 2 terms + f16x2 tanh.
// (R12 version — best measured)
// ---------------------------------------------------------------------------
#define X_STRIDE 136
#define K1_SMEM  174080

__global__ __launch_bounds__(512) void k1_ln_proj_gate(
    const float* __restrict__ feat,
    const float* __restrict__ nw, const float* __restrict__ nb,
    const float* __restrict__ ab, const float* __restrict__ agb,
    const float* __restrict__ gb)
{
    extern __shared__ char sm[];
    __nv_bfloat16* XH = (__nv_bfloat16*)sm;                 // 128*136*2 = 34816
    __nv_bfloat16* XL = (__nv_bfloat16*)(sm + 34816);
    __nv_bfloat16* WH = (__nv_bfloat16*)(sm + 69632);       // 192*136*2 = 52224
    __nv_bfloat16* WL = (__nv_bfloat16*)(sm + 121856);
    __half*        SGATE = (__half*)sm;                     // staging aliases
    __nv_bfloat16* SPH   = (__nv_bfloat16*)(sm + 32768);
    __nv_bfloat16* SPL   = (__nv_bfloat16*)(sm + 40960);

    int t = threadIdx.x, lane = t & 31, wid = t >> 5;
    int base = blockIdx.x * 128;

    // ---- async W prefetch (overlaps LN) ----
    uint32_t wh_b = smaddr(WH), wl_b = smaddr(WL);
    #pragma unroll
    for (int e = 0; e < 6; e++) {
        int idx = t + e*512;
        int n = idx >> 4, q = idx & 15;
        cpasync16(wh_b + (uint32_t)(n*272 + q*16), g_Wbh + n*128 + q*8);
        cpasync16(wl_b + (uint32_t)(n*272 + q*16), g_Wbl + n*128 + q*8);
    }
    CP_COMMIT();

    // ---- layernorm: each warp does 8 rows ----
    {
        float4 w4 = ((const float4*)nw)[lane];
        float4 b4 = ((const float4*)nb)[lane];
        for (int rr = 0; rr < 8; rr++) {
            int row = wid*8 + rr;
            float4 v = ((const float4*)(feat + (size_t)(base+row)*FDIM))[lane];
            float sum = v.x+v.y+v.z+v.w;
            float sq  = v.x*v.x + v.y*v.y + v.z*v.z + v.w*v.w;
            #pragma unroll
            for (int o = 16; o > 0; o >>= 1) {
                sum += __shfl_xor_sync(0xffffffffu, sum, o);
                sq  += __shfl_xor_sync(0xffffffffu, sq,  o);
            }
            float mu   = sum * (1.0f/128.0f);
            float var  = sq  * (1.0f/128.0f) - mu*mu;
            float rstd = rsqrtf(var + 1e-5f);
            float x0 = (v.x-mu)*rstd*w4.x + b4.x;
            float x1 = (v.y-mu)*rstd*w4.y + b4.y;
            float x2 = (v.z-mu)*rstd*w4.z + b4.z;
            float x3 = (v.w-mu)*rstd*w4.w + b4.w;
            __nv_bfloat16 h0=__float2bfloat16(x0), h1=__float2bfloat16(x1),
                          h2=__float2bfloat16(x2), h3=__float2bfloat16(x3);
            __nv_bfloat16 l0=__float2bfloat16(x0-__bfloat162float(h0)),
                          l1=__float2bfloat16(x1-__bfloat162float(h1)),
                          l2=__float2bfloat16(x2-__bfloat162float(h2)),
                          l3=__float2bfloat16(x3-__bfloat162float(h3));
            __nv_bfloat162 hh0 = {h0,h1}, hh1 = {h2,h3};
            __nv_bfloat162 ll0 = {l0,l1}, ll1 = {l2,l3};
            uint2 hp, lp;
            hp.x = *(uint32_t*)&hh0; hp.y = *(uint32_t*)&hh1;
            lp.x = *(uint32_t*)&ll0; lp.y = *(uint32_t*)&ll1;
            *(uint2*)(XH + row*X_STRIDE + lane*4) = hp;
            *(uint2*)(XL + row*X_STRIDE + lane*4) = lp;
        }
    }
    CP_WAIT(0);
    __syncthreads();

    // SMSP-balanced: warpM = SMSP index, warpN varies within each SMSP
    int warpM = wid & 3;
    int warpN = wid >> 2;
    float c[12][4];
    #pragma unroll
    for (int i = 0; i < 12; i++) { c[i][0]=0.f; c[i][1]=0.f; c[i][2]=0.f; c[i][3]=0.f; }

    int grp = lane >> 3, lr = lane & 7;
    int a_row = (grp & 1)*8 + lr, a_k = (grp >> 1)*8;
    int b_row = (grp >> 1)*8 + lr, b_k = (grp & 1)*8;

    uint32_t xh_b = smaddr(XH), xl_b = smaddr(XL);

    for (int kb = 0; kb < 8; kb++) {
        uint32_t ah[2][4], al[2][4], bh[3][4], bl[3][4];
        #pragma unroll
        for (int mt = 0; mt < 2; mt++) {
            uint32_t off = (uint32_t)(((warpM*32 + mt*16 + a_row)*X_STRIDE + kb*16 + a_k)*2);
            ldsm4(ah[mt], xh_b + off);
            ldsm4(al[mt], xl_b + off);
        }
        #pragma unroll
        for (int np = 0; np < 3; np++) {
            uint32_t off = (uint32_t)(((warpN*48 + np*16 + b_row)*X_STRIDE + kb*16 + b_k)*2);
            ldsm4(bh[np], wh_b + off);
            ldsm4(bl[np], wl_b + off);
        }
        #pragma unroll
        for (int mt = 0; mt < 2; mt++)
            #pragma unroll
            for (int nt = 0; nt < 6; nt++) {
                int np = nt >> 1, h = (nt & 1)*2;
                mma_bf16(c[mt*6+nt], ah[mt], bh[np][h], bh[np][h+1]);   // hi*hi
                mma_bf16(c[mt*6+nt], ah[mt], bl[np][h], bl[np][h+1]);   // hi*lo
                if (warpN*48 + nt*8 < 64)
                    mma_bf16(c[mt*6+nt], al[mt], bh[np][h], bh[np][h+1]); // lo*hi (proj only)
            }
    }
    __syncthreads();

    int r0b = warpM*32 + (lane >> 2);
    int cq  = lane & 3;
    #pragma unroll
    for (int mt = 0; mt < 2; mt++) {
        int r0 = r0b + mt*16, r1 = r0 + 8;
        #pragma unroll
        for (int nt = 0; nt < 6; nt++) {
            int nb_ = warpN*48 + nt*8;
            float v0 = c[mt*6+nt][0], v1 = c[mt*6+nt][1];
            float v2 = c[mt*6+nt][2], v3 = c[mt*6+nt][3];
            if (nb_ < 64) {
                int ch = (nb_ >> 1) + cq;
                float abv = ab[ch], agbv = agb[ch];
                float p0 = (v0 + abv) * sigmoidf_(v1 + agbv);
                float p1 = (v2 + abv) * sigmoidf_(v3 + agbv);
                __nv_bfloat16 h0 = __float2bfloat16(p0);
                __nv_bfloat16 h1 = __float2bfloat16(p1);
                SPH[ch*128 + r0] = h0;
                SPH[ch*128 + r1] = h1;
                SPL[ch*128 + r0] = __float2bfloat16(p0 - __bfloat162float(h0));
                SPL[ch*128 + r1] = __float2bfloat16(p1 - __bfloat162float(h1));
            } else {
                int f = nb_ - 64 + 2*cq;
                float zb0 = gb[f], zb1 = gb[f+1];
                __half2 z01 = __floats2half2_rn(v0 + zb0, v1 + zb1);
                __half2 z23 = __floats2half2_rn(v2 + zb0, v3 + zb1);
                *(__half2*)(SGATE + r0*128 + f) = sigmoid2_h2(z01);
                *(__half2*)(SGATE + r1*128 + f) = sigmoid2_h2(z23);
            }
        }
    }
    __syncthreads();

    {
        const float4* sg = (const float4*)SGATE;
        float4* dg = (float4*)(g_gate16 + (size_t)base*FDIM);
        for (int i = t; i < 2048; i += 512) dg[i] = sg[i];
        const float4* sph = (const float4*)SPH;
        const float4* spl = (const float4*)SPL;
        for (int i = t; i < 512; i += 512) {
            int ch = i >> 4, q = i & 15;
            ((float4*)(g_projh + (size_t)ch*LL + base))[q] = sph[i];
            ((float4*)(g_projl + (size_t)ch*LL + base))[q] = spl[i];
        }
    }
}

// ---------------------------------------------------------------------------
// Kernel 2: per-channel SYRK pair = proj proj^T via bf16x3 tensor MMA.
// (R12 version: diag tiles alias B->A, scalar mirror)
// ---------------------------------------------------------------------------
#define K2STRIDE 72
#define K2PLANE  18432
#define K2STAGE  73728
#define K2_SMEM  147456

__global__ __launch_bounds__(512) void k2_einsum()
{
    extern __shared__ char sm[];
    uint32_t sbase = smaddr(sm);

    int t = threadIdx.x, lane = t & 31, wid = t >> 5;
    int warpM = wid >> 2, warpN = wid & 3;
    int ch = blockIdx.y;

    int tt = blockIdx.x, bi = 0;
    while (tt >= 6 - bi) { tt -= 6 - bi; bi++; }
    int bj = bi + tt;
    int i0 = bi*128, j0 = bj*128;
    bool diag = (bi == bj);

    const __nv_bfloat16* Ph = g_projh + (size_t)ch*LL;
    const __nv_bfloat16* Pl = g_projl + (size_t)ch*LL;
    const __nv_bfloat16* psrc[4];
    int rowbase[4];
    psrc[0] = Ph; rowbase[0] = i0;
    psrc[1] = Pl; rowbase[1] = i0;
    psrc[2] = Ph; rowbase[2] = j0;
    psrc[3] = Pl; rowbase[3] = j0;

    auto load_chunk = [&](int c, int s) {
        int k0 = c*64;
        uint32_t dst0 = sbase + s*K2STAGE;
        #pragma unroll
        for (int e = 0; e < 8; e++) {
            if (diag && e >= 4) continue;
            int idx = t + e*512;
            int plane = idx >> 10;
            int r = (idx >> 3) & 127;
            int q = idx & 7;
            cpasync16(dst0 + (uint32_t)(plane*K2PLANE + r*144 + q*16),
                      psrc[plane] + (size_t)(rowbase[plane] + r)*LDIM + k0 + q*8);
        }
        CP_COMMIT();
    };

    float c[8][4];
    #pragma unroll
    for (int i = 0; i < 8; i++) { c[i][0]=0.f; c[i][1]=0.f; c[i][2]=0.f; c[i][3]=0.f; }

    int grp = lane >> 3, lr = lane & 7;
    int a_row = (grp & 1)*8 + lr, a_k = (grp >> 1)*8;
    int b_row = (grp >> 1)*8 + lr, b_k = (grp & 1)*8;

    load_chunk(0, 0);
    load_chunk(1, 1);

    for (int cidx = 0; cidx < 12; cidx++) {
        if (cidx < 11) { CP_WAIT(1); } else { CP_WAIT(0); }
        __syncthreads();

        int s = cidx & 1;
        uint32_t ah_b = sbase + s*K2STAGE;
        uint32_t al_b = ah_b + K2PLANE;
        uint32_t bh_b = diag ? ah_b : (ah_b + 2*K2PLANE);
        uint32_t bl_b = diag ? al_b : (ah_b + 3*K2PLANE);

        #pragma unroll
        for (int kb = 0; kb < 4; kb++) {
            uint32_t ah[2][4], al[2][4], bh[2][4], bl[2][4];
            #pragma unroll
            for (int mt = 0; mt < 2; mt++) {
                uint32_t off = (uint32_t)(((warpM*32 + mt*16 + a_row)*K2STRIDE + kb*16 + a_k)*2);
                ldsm4(ah[mt], ah_b + off);
                ldsm4(al[mt], al_b + off);
            }
            #pragma unroll
            for (int np = 0; np < 2; np++) {
                uint32_t off = (uint32_t)(((warpN*32 + np*16 + b_row)*K2STRIDE + kb*16 + b_k)*2);
                ldsm4(bh[np], bh_b + off);
                ldsm4(bl[np], bl_b + off);
            }
            #pragma unroll
            for (int mt = 0; mt < 2; mt++)
                #pragma unroll
                for (int nt = 0; nt < 4; nt++) {
                    int np = nt >> 1, h = (nt & 1)*2;
                    mma_bf16(c[mt*4+nt], ah[mt], bh[np][h], bh[np][h+1]);
                    mma_bf16(c[mt*4+nt], ah[mt], bl[np][h], bl[np][h+1]);
                    mma_bf16(c[mt*4+nt], al[mt], bh[np][h], bh[np][h+1]);
                }
        }
        __syncthreads();
        if (cidx + 2 < 12) load_chunk(cidx + 2, s);
    }

    float* Cc = g_pair + (size_t)ch*LL;
    #pragma unroll
    for (int mt = 0; mt < 2; mt++) {
        int r = i0 + warpM*32 + mt*16 + (lane >> 2);
        #pragma unroll
        for (int nt = 0; nt < 4; nt++) {
            int col = j0 + warpN*32 + nt*8 + 2*(lane & 3);
            float2 v01 = make_float2(c[mt*4+nt][0], c[mt*4+nt][1]);
            float2 v23 = make_float2(c[mt*4+nt][2], c[mt*4+nt][3]);
            *(float2*)(Cc + (size_t)r*LDIM + col)     = v01;
            *(float2*)(Cc + (size_t)(r+8)*LDIM + col) = v23;
            if (!diag) {
                Cc[(size_t)col*LDIM     + r]   = v01.x;
                Cc[(size_t)(col+1)*LDIM + r]   = v01.y;
                Cc[(size_t)col*LDIM     + r+8] = v23.x;
                Cc[(size_t)(col+1)*LDIM + r+8] = v23.y;
            }
        }
    }
}

// ---------------------------------------------------------------------------
// Kernel 3: out = (LN_P(pair) @ oW^T + ob) * gate. 256 threads / 128 positions.
// NEW: epilogue stages out-tile in smem, then fully-coalesced gate-read /
// out-write (one row per warp instruction) — cuts L1tex wavefronts ~4x.
// ---------------------------------------------------------------------------
#define A_STRIDE 40
#define K3_SMEM  69632

__global__ __launch_bounds__(256) void k3_out(
    const float* __restrict__ onw, const float* __restrict__ onb,
    const float* __restrict__ oW, const float* __restrict__ ob,
    float* __restrict__ out)
{
    extern __shared__ char sm[];
    __nv_bfloat16* AH = (__nv_bfloat16*)sm;
    __nv_bfloat16* AL = (__nv_bfloat16*)(sm + 10240);
    __nv_bfloat16* BH = (__nv_bfloat16*)(sm + 20480);
    __nv_bfloat16* BL = (__nv_bfloat16*)(sm + 30720);

    int t = threadIdx.x, lane = t & 31, wid = t >> 5;
    int i  = blockIdx.y;
    int j0 = blockIdx.x * 128;
    size_t posbase = (size_t)i*LDIM + j0;

    if (t < 128) {
        int jj = t;
        float y[32];
        float sum = 0.f, sq = 0.f;
        #pragma unroll
        for (int cc = 0; cc < 32; cc++) {
            y[cc] = g_pair[(size_t)cc*LL + posbase + jj];
            sum += y[cc];
            sq  += y[cc]*y[cc];
        }
        float mu   = sum * (1.0f/32.0f);
        float var  = sq  * (1.0f/32.0f) - mu*mu;
        float rstd = rsqrtf(var + 1e-5f);
        #pragma unroll
        for (int q = 0; q < 16; q++) {
            float v0 = (y[2*q]  -mu)*rstd*onw[2*q]   + onb[2*q];
            float v1 = (y[2*q+1]-mu)*rstd*onw[2*q+1] + onb[2*q+1];
            __nv_bfloat16 h0 = __float2bfloat16(v0);
            __nv_bfloat16 h1 = __float2bfloat16(v1);
            __nv_bfloat162 hh = {h0, h1};
            __nv_bfloat162 ll = {__float2bfloat16(v0 - __bfloat162float(h0)),
                                 __float2bfloat16(v1 - __bfloat162float(h1))};
            *(uint32_t*)(AH + jj*A_STRIDE + 2*q) = *(uint32_t*)&hh;
            *(uint32_t*)(AL + jj*A_STRIDE + 2*q) = *(uint32_t*)&ll;
        }
    } else {
        int t2 = t - 128;
        #pragma unroll
        for (int e = 0; e < 32; e++) {
            int idx = t2 + e*128;
            int f = idx >> 5, c2 = idx & 31;
            float w = oW[idx];
            __nv_bfloat16 wh = __float2bfloat16(w);
            BH[f*A_STRIDE + c2] = wh;
            BL[f*A_STRIDE + c2] = __float2bfloat16(w - __bfloat162float(wh));
        }
    }
    __syncthreads();

    int warpM = wid >> 2, warpN = wid & 3;
    float c[16][4];
    #pragma unroll
    for (int q = 0; q < 16; q++) { c[q][0]=0.f; c[q][1]=0.f; c[q][2]=0.f; c[q][3]=0.f; }

    int grp = lane >> 3, lr = lane & 7;
    int a_row = (grp & 1)*8 + lr, a_k = (grp >> 1)*8;
    int b_row = (grp >> 1)*8 + lr, b_k = (grp & 1)*8;

    uint32_t ah_b = smaddr(AH), al_b = smaddr(AL);
    uint32_t bh_b = smaddr(BH), bl_b = smaddr(BL);

    #pragma unroll
    for (int kb = 0; kb < 2; kb++) {
        uint32_t ah[4][4], al[4][4], bh[2][4], bl[2][4];
        #pragma unroll
        for (int mt = 0; mt < 4; mt++) {
            uint32_t off = (uint32_t)(((warpM*64 + mt*16 + a_row)*A_STRIDE + kb*16 + a_k)*2);
            ldsm4(ah[mt], ah_b + off);
            ldsm4(al[mt], al_b + off);
        }
        #pragma unroll
        for (int np = 0; np < 2; np++) {
            uint32_t off = (uint32_t)(((warpN*32 + np*16 + b_row)*A_STRIDE + kb*16 + b_k)*2);
            ldsm4(bh[np], bh_b + off);
            ldsm4(bl[np], bl_b + off);
        }
        #pragma unroll
        for (int mt = 0; mt < 4; mt++)
            #pragma unroll
            for (int nt = 0; nt < 4; nt++) {
                int np = nt >> 1, h = (nt & 1)*2;
                mma_bf16(c[mt*4+nt], ah[mt], bh[np][h], bh[np][h+1]);
                mma_bf16(c[mt*4+nt], ah[mt], bl[np][h], bl[np][h+1]);
                mma_bf16(c[mt*4+nt], al[mt], bh[np][h], bh[np][h+1]);
            }
    }

    // ---- stage out-tile in smem (aliases A/B buffers, now dead) ----
    __syncthreads();
    float* OUT = (float*)sm;                 // [128][132]
    #pragma unroll
    for (int mt = 0; mt < 4; mt++) {
        int r = warpM*64 + mt*16 + (lane >> 2);
        #pragma unroll
        for (int nt = 0; nt < 4; nt++) {
            int col = warpN*32 + nt*8 + 2*(lane & 3);
            *(float2*)(OUT + r*132 + col)     = make_float2(c[mt*4+nt][0], c[mt*4+nt][1]);
            *(float2*)(OUT + (r+8)*132 + col) = make_float2(c[mt*4+nt][2], c[mt*4+nt][3]);
        }
    }
    __syncthreads();

    // ---- coalesced flush: warp instruction = exactly one row ----
    #pragma unroll
    for (int k = 0; k < 16; k++) {
        int idx = t + k*256;                 // 0..4095 float4 slots
        int row = idx >> 5, q = idx & 31;
        int col = q*4;
        float4 v   = *(float4*)(OUT + row*132 + col);
        float4 obv = *(const float4*)(ob + col);
        size_t o = (posbase + row)*FDIM + col;
        uint2 g2 = *(const uint2*)(g_gate16 + o);
        float2 gA = __half22float2(*(__half2*)&g2.x);
        float2 gB = __half22float2(*(__half2*)&g2.y);
        float4 r;
        r.x = (v.x + obv.x)*gA.x;
        r.y = (v.y + obv.y)*gA.y;
        r.z = (v.z + obv.z)*gB.x;
        r.w = (v.w + obv.w)*gB.y;
        *(float4*)(out + o) = r;
    }
}

// ---------------------------------------------------------------------------
extern "C" void kernel_launch(void* const* d_in, const int* in_sizes, int n_in,
                              void* d_out, int out_size)
{
    const float* feat = (const float*)d_in[0];
    const float* nw   = (const float*)d_in[1];
    const float* nb   = (const float*)d_in[2];
    const float* onw  = (const float*)d_in[3];
    const float* onb  = (const float*)d_in[4];
    const float* aW   = (const float*)d_in[5];
    const float* ab   = (const float*)d_in[6];
    const float* agW  = (const float*)d_in[7];
    const float* agb  = (const float*)d_in[8];
    const float* oW   = (const float*)d_in[9];
    const float* ob   = (const float*)d_in[10];
    const float* gW   = (const float*)d_in[11];
    const float* gb   = (const float*)d_in[12];
    float* out = (float*)d_out;

    cudaFuncSetAttribute(k1_ln_proj_gate, cudaFuncAttributeMaxDynamicSharedMemorySize, K1_SMEM);
    cudaFuncSetAttribute(k2_einsum,       cudaFuncAttributeMaxDynamicSharedMemorySize, K2_SMEM);
    cudaFuncSetAttribute(k3_out,          cudaFuncAttributeMaxDynamicSharedMemorySize, K3_SMEM);

    k_pack<<<96, 256>>>(aW, agW, gW);
    k1_ln_proj_gate<<<LL/128, 512, K1_SMEM>>>(feat, nw, nb, ab, agb, gb);
    k2_einsum<<<dim3(21, 32), 512, K2_SMEM>>>();
    k3_out<<<dim3(6, 768), 256, K3_SMEM>>>(onw, onb, oW, ob, out);
}

// round 16
// speedup vs baseline: 1.1128x; 1.1128x over previous
#include <cuda_runtime.h>
#include <cuda_bf16.h>
#include <cuda_fp16.h>
#include <cstdint>

#define LDIM 768
#define LL   (768*768)
#define FDIM 128
#define PDIM 32

// ---------------- device scratch (allocation-free rule) ----------------
__device__ __nv_bfloat16 g_Wbh[192*128];            // reordered weights hi [n][k]
__device__ __nv_bfloat16 g_Wbl[192*128];            // reordered weights lo [n][k]
__device__ __nv_bfloat16 g_projh[(size_t)PDIM*LL];  // proj hi, channel-major [c][pos]
__device__ __nv_bfloat16 g_projl[(size_t)PDIM*LL];  // proj lo
__device__ float         g_pair[(size_t)PDIM*LL];   // pair, channel-major [c][i*L+j]
__device__ __half        g_gate16[(size_t)LL*FDIM]; // gate fp16 [pos][f]

// precise sigmoid (proj path: feeds LN-amplified einsum)
__device__ __forceinline__ float sigmoidf_(float x) { return 1.0f/(1.0f + __expf(-x)); }

__device__ __forceinline__ void ldsm4(uint32_t (&r)[4], uint32_t addr) {
    asm volatile("ldmatrix.sync.aligned.m8n8.x4.shared.b16 {%0,%1,%2,%3}, [%4];"
        : "=r"(r[0]), "=r"(r[1]), "=r"(r[2]), "=r"(r[3]) : "r"(addr));
}
__device__ __forceinline__ void mma_bf16(float (&c)[4], const uint32_t (&a)[4],
                                         uint32_t b0, uint32_t b1) {
    asm volatile("mma.sync.aligned.m16n8k16.row.col.f32.bf16.bf16.f32 "
        "{%0,%1,%2,%3},{%4,%5,%6,%7},{%8,%9},{%0,%1,%2,%3};"
        : "+f"(c[0]), "+f"(c[1]), "+f"(c[2]), "+f"(c[3])
        : "r"(a[0]), "r"(a[1]), "r"(a[2]), "r"(a[3]), "r"(b0), "r"(b1));
}
__device__ __forceinline__ uint32_t smaddr(const void* p) {
    return (uint32_t)__cvta_generic_to_shared(p);
}
__device__ __forceinline__ void cpasync16(uint32_t dst, const void* src) {
    asm volatile("cp.async.cg.shared.global [%0], [%1], 16;" :: "r"(dst), "l"(src));
}
#define CP_COMMIT()  asm volatile("cp.async.commit_group;")
#define CP_WAIT(n)   asm volatile("cp.async.wait_group %0;" :: "n"(n))

// packed fp16 sigmoid: sigma(z) = 0.5*tanh(z/2)+0.5, two lanes per MUFU
__device__ __forceinline__ __half2 sigmoid2_h2(__half2 z) {
    const __half2 h05 = __float2half2_rn(0.5f);
    __half2 zh = __hmul2(z, h05);
    uint32_t tt;
    asm("tanh.approx.f16x2 %0, %1;" : "=r"(tt) : "r"(*(uint32_t*)&zh));
    return __hfma2(*(__half2*)&tt, h05, h05);
}

// ---------------------------------------------------------------------------
// Kernel 0: pack weights -> bf16 hi/lo planes, [n][k] layout.
// ---------------------------------------------------------------------------
__global__ void k_pack(const float* __restrict__ aW, const float* __restrict__ agW,
                       const float* __restrict__ gW)
{
    int idx = blockIdx.x * 256 + threadIdx.x;
    if (idx >= 192*128) return;
    int n = idx >> 7, k = idx & 127;
    float v;
    if (n < 64) { int ch = n >> 1; v = (n & 1) ? agW[ch*FDIM + k] : aW[ch*FDIM + k]; }
    else        { v = gW[(n-64)*FDIM + k]; }
    __nv_bfloat16 vh = __float2bfloat16(v);
    __nv_bfloat16 vl = __float2bfloat16(v - __bfloat162float(vh));
    g_Wbh[idx] = vh;
    g_Wbl[idx] = vl;
}

// ---------------------------------------------------------------------------
// Kernel 1: LN(F) + X[128,128] @ Wcat[128,192] via bf16 tensor MMA.
// 512 threads = 16 warps; warp tile 32x48. SMSP-balanced mapping.
// proj cols (<64): 3 terms + precise sigmoid; gate cols: 2 terms + f16x2 tanh.
// (R12 version — best measured)
// ---------------------------------------------------------------------------
#define X_STRIDE 136
#define K1_SMEM  174080

__global__ __launch_bounds__(512) void k1_ln_proj_gate(
    const float* __restrict__ feat,
    const float* __restrict__ nw, const float* __restrict__ nb,
    const float* __restrict__ ab, const float* __restrict__ agb,
    const float* __restrict__ gb)
{
    extern __shared__ char sm[];
    __nv_bfloat16* XH = (__nv_bfloat16*)sm;                 // 128*136*2 = 34816
    __nv_bfloat16* XL = (__nv_bfloat16*)(sm + 34816);
    __nv_bfloat16* WH = (__nv_bfloat16*)(sm + 69632);       // 192*136*2 = 52224
    __nv_bfloat16* WL = (__nv_bfloat16*)(sm + 121856);
    __half*        SGATE = (__half*)sm;                     // staging aliases
    __nv_bfloat16* SPH   = (__nv_bfloat16*)(sm + 32768);
    __nv_bfloat16* SPL   = (__nv_bfloat16*)(sm + 40960);

    int t = threadIdx.x, lane = t & 31, wid = t >> 5;
    int base = blockIdx.x * 128;

    // ---- async W prefetch (overlaps LN) ----
    uint32_t wh_b = smaddr(WH), wl_b = smaddr(WL);
    #pragma unroll
    for (int e = 0; e < 6; e++) {
        int idx = t + e*512;
        int n = idx >> 4, q = idx & 15;
        cpasync16(wh_b + (uint32_t)(n*272 + q*16), g_Wbh + n*128 + q*8);
        cpasync16(wl_b + (uint32_t)(n*272 + q*16), g_Wbl + n*128 + q*8);
    }
    CP_COMMIT();

    // ---- layernorm: each warp does 8 rows ----
    {
        float4 w4 = ((const float4*)nw)[lane];
        float4 b4 = ((const float4*)nb)[lane];
        for (int rr = 0; rr < 8; rr++) {
            int row = wid*8 + rr;
            float4 v = ((const float4*)(feat + (size_t)(base+row)*FDIM))[lane];
            float sum = v.x+v.y+v.z+v.w;
            float sq  = v.x*v.x + v.y*v.y + v.z*v.z + v.w*v.w;
            #pragma unroll
            for (int o = 16; o > 0; o >>= 1) {
                sum += __shfl_xor_sync(0xffffffffu, sum, o);
                sq  += __shfl_xor_sync(0xffffffffu, sq,  o);
            }
            float mu   = sum * (1.0f/128.0f);
            float var  = sq  * (1.0f/128.0f) - mu*mu;
            float rstd = rsqrtf(var + 1e-5f);
            float x0 = (v.x-mu)*rstd*w4.x + b4.x;
            float x1 = (v.y-mu)*rstd*w4.y + b4.y;
            float x2 = (v.z-mu)*rstd*w4.z + b4.z;
            float x3 = (v.w-mu)*rstd*w4.w + b4.w;
            __nv_bfloat16 h0=__float2bfloat16(x0), h1=__float2bfloat16(x1),
                          h2=__float2bfloat16(x2), h3=__float2bfloat16(x3);
            __nv_bfloat16 l0=__float2bfloat16(x0-__bfloat162float(h0)),
                          l1=__float2bfloat16(x1-__bfloat162float(h1)),
                          l2=__float2bfloat16(x2-__bfloat162float(h2)),
                          l3=__float2bfloat16(x3-__bfloat162float(h3));
            __nv_bfloat162 hh0 = {h0,h1}, hh1 = {h2,h3};
            __nv_bfloat162 ll0 = {l0,l1}, ll1 = {l2,l3};
            uint2 hp, lp;
            hp.x = *(uint32_t*)&hh0; hp.y = *(uint32_t*)&hh1;
            lp.x = *(uint32_t*)&ll0; lp.y = *(uint32_t*)&ll1;
            *(uint2*)(XH + row*X_STRIDE + lane*4) = hp;
            *(uint2*)(XL + row*X_STRIDE + lane*4) = lp;
        }
    }
    CP_WAIT(0);
    __syncthreads();

    // SMSP-balanced: warpM = SMSP index, warpN varies within each SMSP
    int warpM = wid & 3;
    int warpN = wid >> 2;
    float c[12][4];
    #pragma unroll
    for (int i = 0; i < 12; i++) { c[i][0]=0.f; c[i][1]=0.f; c[i][2]=0.f; c[i][3]=0.f; }

    int grp = lane >> 3, lr = lane & 7;
    int a_row = (grp & 1)*8 + lr, a_k = (grp >> 1)*8;
    int b_row = (grp >> 1)*8 + lr, b_k = (grp & 1)*8;

    uint32_t xh_b = smaddr(XH), xl_b = smaddr(XL);

    for (int kb = 0; kb < 8; kb++) {
        uint32_t ah[2][4], al[2][4], bh[3][4], bl[3][4];
        #pragma unroll
        for (int mt = 0; mt < 2; mt++) {
            uint32_t off = (uint32_t)(((warpM*32 + mt*16 + a_row)*X_STRIDE + kb*16 + a_k)*2);
            ldsm4(ah[mt], xh_b + off);
            ldsm4(al[mt], xl_b + off);
        }
        #pragma unroll
        for (int np = 0; np < 3; np++) {
            uint32_t off = (uint32_t)(((warpN*48 + np*16 + b_row)*X_STRIDE + kb*16 + b_k)*2);
            ldsm4(bh[np], wh_b + off);
            ldsm4(bl[np], wl_b + off);
        }
        #pragma unroll
        for (int mt = 0; mt < 2; mt++)
            #pragma unroll
            for (int nt = 0; nt < 6; nt++) {
                int np = nt >> 1, h = (nt & 1)*2;
                mma_bf16(c[mt*6+nt], ah[mt], bh[np][h], bh[np][h+1]);   // hi*hi
                mma_bf16(c[mt*6+nt], ah[mt], bl[np][h], bl[np][h+1]);   // hi*lo
                if (warpN*48 + nt*8 < 64)
                    mma_bf16(c[mt*6+nt], al[mt], bh[np][h], bh[np][h+1]); // lo*hi (proj only)
            }
    }
    __syncthreads();

    int r0b = warpM*32 + (lane >> 2);
    int cq  = lane & 3;
    #pragma unroll
    for (int mt = 0; mt < 2; mt++) {
        int r0 = r0b + mt*16, r1 = r0 + 8;
        #pragma unroll
        for (int nt = 0; nt < 6; nt++) {
            int nb_ = warpN*48 + nt*8;
            float v0 = c[mt*6+nt][0], v1 = c[mt*6+nt][1];
            float v2 = c[mt*6+nt][2], v3 = c[mt*6+nt][3];
            if (nb_ < 64) {
                int ch = (nb_ >> 1) + cq;
                float abv = ab[ch], agbv = agb[ch];
                float p0 = (v0 + abv) * sigmoidf_(v1 + agbv);
                float p1 = (v2 + abv) * sigmoidf_(v3 + agbv);
                __nv_bfloat16 h0 = __float2bfloat16(p0);
                __nv_bfloat16 h1 = __float2bfloat16(p1);
                SPH[ch*128 + r0] = h0;
                SPH[ch*128 + r1] = h1;
                SPL[ch*128 + r0] = __float2bfloat16(p0 - __bfloat162float(h0));
                SPL[ch*128 + r1] = __float2bfloat16(p1 - __bfloat162float(h1));
            } else {
                int f = nb_ - 64 + 2*cq;
                float zb0 = gb[f], zb1 = gb[f+1];
                __half2 z01 = __floats2half2_rn(v0 + zb0, v1 + zb1);
                __half2 z23 = __floats2half2_rn(v2 + zb0, v3 + zb1);
                *(__half2*)(SGATE + r0*128 + f) = sigmoid2_h2(z01);
                *(__half2*)(SGATE + r1*128 + f) = sigmoid2_h2(z23);
            }
        }
    }
    __syncthreads();

    {
        const float4* sg = (const float4*)SGATE;
        float4* dg = (float4*)(g_gate16 + (size_t)base*FDIM);
        for (int i = t; i < 2048; i += 512) dg[i] = sg[i];
        const float4* sph = (const float4*)SPH;
        const float4* spl = (const float4*)SPL;
        for (int i = t; i < 512; i += 512) {
            int ch = i >> 4, q = i & 15;
            ((float4*)(g_projh + (size_t)ch*LL + base))[q] = sph[i];
            ((float4*)(g_projl + (size_t)ch*LL + base))[q] = spl[i];
        }
    }
}

// ---------------------------------------------------------------------------
// Kernel 2: per-channel SYRK pair = proj proj^T via bf16x3 tensor MMA.
// (R12 version: diag tiles alias B->A, scalar mirror)
// ---------------------------------------------------------------------------
#define K2STRIDE 72
#define K2PLANE  18432
#define K2STAGE  73728
#define K2_SMEM  147456

__global__ __launch_bounds__(512) void k2_einsum()
{
    extern __shared__ char sm[];
    uint32_t sbase = smaddr(sm);

    int t = threadIdx.x, lane = t & 31, wid = t >> 5;
    int warpM = wid >> 2, warpN = wid & 3;
    int ch = blockIdx.y;

    int tt = blockIdx.x, bi = 0;
    while (tt >= 6 - bi) { tt -= 6 - bi; bi++; }
    int bj = bi + tt;
    int i0 = bi*128, j0 = bj*128;
    bool diag = (bi == bj);

    const __nv_bfloat16* Ph = g_projh + (size_t)ch*LL;
    const __nv_bfloat16* Pl = g_projl + (size_t)ch*LL;
    const __nv_bfloat16* psrc[4];
    int rowbase[4];
    psrc[0] = Ph; rowbase[0] = i0;
    psrc[1] = Pl; rowbase[1] = i0;
    psrc[2] = Ph; rowbase[2] = j0;
    psrc[3] = Pl; rowbase[3] = j0;

    auto load_chunk = [&](int c, int s) {
        int k0 = c*64;
        uint32_t dst0 = sbase + s*K2STAGE;
        #pragma unroll
        for (int e = 0; e < 8; e++) {
            if (diag && e >= 4) continue;
            int idx = t + e*512;
            int plane = idx >> 10;
            int r = (idx >> 3) & 127;
            int q = idx & 7;
            cpasync16(dst0 + (uint32_t)(plane*K2PLANE + r*144 + q*16),
                      psrc[plane] + (size_t)(rowbase[plane] + r)*LDIM + k0 + q*8);
        }
        CP_COMMIT();
    };

    float c[8][4];
    #pragma unroll
    for (int i = 0; i < 8; i++) { c[i][0]=0.f; c[i][1]=0.f; c[i][2]=0.f; c[i][3]=0.f; }

    int grp = lane >> 3, lr = lane & 7;
    int a_row = (grp & 1)*8 + lr, a_k = (grp >> 1)*8;
    int b_row = (grp >> 1)*8 + lr, b_k = (grp & 1)*8;

    load_chunk(0, 0);
    load_chunk(1, 1);

    for (int cidx = 0; cidx < 12; cidx++) {
        if (cidx < 11) { CP_WAIT(1); } else { CP_WAIT(0); }
        __syncthreads();

        int s = cidx & 1;
        uint32_t ah_b = sbase + s*K2STAGE;
        uint32_t al_b = ah_b + K2PLANE;
        uint32_t bh_b = diag ? ah_b : (ah_b + 2*K2PLANE);
        uint32_t bl_b = diag ? al_b : (ah_b + 3*K2PLANE);

        #pragma unroll
        for (int kb = 0; kb < 4; kb++) {
            uint32_t ah[2][4], al[2][4], bh[2][4], bl[2][4];
            #pragma unroll
            for (int mt = 0; mt < 2; mt++) {
                uint32_t off = (uint32_t)(((warpM*32 + mt*16 + a_row)*K2STRIDE + kb*16 + a_k)*2);
                ldsm4(ah[mt], ah_b + off);
                ldsm4(al[mt], al_b + off);
            }
            #pragma unroll
            for (int np = 0; np < 2; np++) {
                uint32_t off = (uint32_t)(((warpN*32 + np*16 + b_row)*K2STRIDE + kb*16 + b_k)*2);
                ldsm4(bh[np], bh_b + off);
                ldsm4(bl[np], bl_b + off);
            }
            #pragma unroll
            for (int mt = 0; mt < 2; mt++)
                #pragma unroll
                for (int nt = 0; nt < 4; nt++) {
                    int np = nt >> 1, h = (nt & 1)*2;
                    mma_bf16(c[mt*4+nt], ah[mt], bh[np][h], bh[np][h+1]);
                    mma_bf16(c[mt*4+nt], ah[mt], bl[np][h], bl[np][h+1]);
                    mma_bf16(c[mt*4+nt], al[mt], bh[np][h], bh[np][h+1]);
                }
        }
        __syncthreads();
        if (cidx + 2 < 12) load_chunk(cidx + 2, s);
    }

    float* Cc = g_pair + (size_t)ch*LL;
    #pragma unroll
    for (int mt = 0; mt < 2; mt++) {
        int r = i0 + warpM*32 + mt*16 + (lane >> 2);
        #pragma unroll
        for (int nt = 0; nt < 4; nt++) {
            int col = j0 + warpN*32 + nt*8 + 2*(lane & 3);
            float2 v01 = make_float2(c[mt*4+nt][0], c[mt*4+nt][1]);
            float2 v23 = make_float2(c[mt*4+nt][2], c[mt*4+nt][3]);
            *(float2*)(Cc + (size_t)r*LDIM + col)     = v01;
            *(float2*)(Cc + (size_t)(r+8)*LDIM + col) = v23;
            if (!diag) {
                Cc[(size_t)col*LDIM     + r]   = v01.x;
                Cc[(size_t)(col+1)*LDIM + r]   = v01.y;
                Cc[(size_t)col*LDIM     + r+8] = v23.x;
                Cc[(size_t)(col+1)*LDIM + r+8] = v23.y;
            }
        }
    }
}

// ---------------------------------------------------------------------------
// Kernel 3: out = (LN_P(pair) @ oW^T + ob) * gate. 256 threads / 128 positions.
// R12 structure + cp.async gate prefetch. GT_STRIDE=136 halves (272B rows,
// 16B-aligned for cp.async; 4-bank row rotation).
// ---------------------------------------------------------------------------
#define A_STRIDE 40
#define GT_STRIDE 136
#define K3_SMEM  75776        // 40960 (A/B) + 128*136*2 (gate)

__global__ __launch_bounds__(256) void k3_out(
    const float* __restrict__ onw, const float* __restrict__ onb,
    const float* __restrict__ oW, const float* __restrict__ ob,
    float* __restrict__ out)
{
    extern __shared__ char sm[];
    __nv_bfloat16* AH = (__nv_bfloat16*)sm;
    __nv_bfloat16* AL = (__nv_bfloat16*)(sm + 10240);
    __nv_bfloat16* BH = (__nv_bfloat16*)(sm + 20480);
    __nv_bfloat16* BL = (__nv_bfloat16*)(sm + 30720);
    __half*        GT = (__half*)(sm + 40960);   // [128][GT_STRIDE]

    int t = threadIdx.x, lane = t & 31, wid = t >> 5;
    int i  = blockIdx.y;
    int j0 = blockIdx.x * 128;
    size_t posbase = (size_t)i*LDIM + j0;

    // ---- async gate prefetch: 128 rows x 128 halves = 2048 x 16B ----
    {
        uint32_t gt_b = smaddr(GT);
        #pragma unroll
        for (int e = 0; e < 8; e++) {
            int idx = t + e*256;
            int row = idx >> 4, q = idx & 15;
            cpasync16(gt_b + (uint32_t)((row*GT_STRIDE + q*8)*2),
                      g_gate16 + (posbase + row)*FDIM + q*8);
        }
        CP_COMMIT();
    }

    if (t < 128) {
        int jj = t;
        float y[32];
        float sum = 0.f, sq = 0.f;
        #pragma unroll
        for (int cc = 0; cc < 32; cc++) {
            y[cc] = g_pair[(size_t)cc*LL + posbase + jj];
            sum += y[cc];
            sq  += y[cc]*y[cc];
        }
        float mu   = sum * (1.0f/32.0f);
        float var  = sq  * (1.0f/32.0f) - mu*mu;
        float rstd = rsqrtf(var + 1e-5f);
        #pragma unroll
        for (int q = 0; q < 16; q++) {
            float v0 = (y[2*q]  -mu)*rstd*onw[2*q]   + onb[2*q];
            float v1 = (y[2*q+1]-mu)*rstd*onw[2*q+1] + onb[2*q+1];
            __nv_bfloat16 h0 = __float2bfloat16(v0);
            __nv_bfloat16 h1 = __float2bfloat16(v1);
            __nv_bfloat162 hh = {h0, h1};
            __nv_bfloat162 ll = {__float2bfloat16(v0 - __bfloat162float(h0)),
                                 __float2bfloat16(v1 - __bfloat162float(h1))};
            *(uint32_t*)(AH + jj*A_STRIDE + 2*q) = *(uint32_t*)&hh;
            *(uint32_t*)(AL + jj*A_STRIDE + 2*q) = *(uint32_t*)&ll;
        }
    } else {
        int t2 = t - 128;
        #pragma unroll
        for (int e = 0; e < 32; e++) {
            int idx = t2 + e*128;
            int f = idx >> 5, c2 = idx & 31;
            float w = oW[idx];
            __nv_bfloat16 wh = __float2bfloat16(w);
            BH[f*A_STRIDE + c2] = wh;
            BL[f*A_STRIDE + c2] = __float2bfloat16(w - __bfloat162float(wh));
        }
    }
    __syncthreads();

    int warpM = wid >> 2, warpN = wid & 3;
    float c[16][4];
    #pragma unroll
    for (int q = 0; q < 16; q++) { c[q][0]=0.f; c[q][1]=0.f; c[q][2]=0.f; c[q][3]=0.f; }

    int grp = lane >> 3, lr = lane & 7;
    int a_row = (grp & 1)*8 + lr, a_k = (grp >> 1)*8;
    int b_row = (grp >> 1)*8 + lr, b_k = (grp & 1)*8;

    uint32_t ah_b = smaddr(AH), al_b = smaddr(AL);
    uint32_t bh_b = smaddr(BH), bl_b = smaddr(BL);

    #pragma unroll
    for (int kb = 0; kb < 2; kb++) {
        uint32_t ah[4][4], al[4][4], bh[2][4], bl[2][4];
        #pragma unroll
        for (int mt = 0; mt < 4; mt++) {
            uint32_t off = (uint32_t)(((warpM*64 + mt*16 + a_row)*A_STRIDE + kb*16 + a_k)*2);
            ldsm4(ah[mt], ah_b + off);
            ldsm4(al[mt], al_b + off);
        }
        #pragma unroll
        for (int np = 0; np < 2; np++) {
            uint32_t off = (uint32_t)(((warpN*32 + np*16 + b_row)*A_STRIDE + kb*16 + b_k)*2);
            ldsm4(bh[np], bh_b + off);
            ldsm4(bl[np], bl_b + off);
        }
        #pragma unroll
        for (int mt = 0; mt < 4; mt++)
            #pragma unroll
            for (int nt = 0; nt < 4; nt++) {
                int np = nt >> 1, h = (nt & 1)*2;
                mma_bf16(c[mt*4+nt], ah[mt], bh[np][h], bh[np][h+1]);
                mma_bf16(c[mt*4+nt], ah[mt], bl[np][h], bl[np][h+1]);
                mma_bf16(c[mt*4+nt], al[mt], bh[np][h], bh[np][h+1]);
            }
    }

    // ensure prefetched gate visible to all threads
    CP_WAIT(0);
    __syncthreads();

    #pragma unroll
    for (int mt = 0; mt < 4; mt++) {
        int r = warpM*64 + mt*16 + (lane >> 2);
        #pragma unroll
        for (int nt = 0; nt < 4; nt++) {
            int col = warpN*32 + nt*8 + 2*(lane & 3);
            float ob0 = ob[col], ob1 = ob[col+1];
            size_t o0 = (posbase + r)*FDIM + col;
            size_t o1 = o0 + (size_t)8*FDIM;
            __half2 gh0 = *(const __half2*)(GT + r*GT_STRIDE + col);
            __half2 gh1 = *(const __half2*)(GT + (r+8)*GT_STRIDE + col);
            float2 g0 = __half22float2(gh0);
            float2 g1 = __half22float2(gh1);
            float2 r0 = make_float2((c[mt*4+nt][0] + ob0)*g0.x, (c[mt*4+nt][1] + ob1)*g0.y);
            float2 r1 = make_float2((c[mt*4+nt][2] + ob0)*g1.x, (c[mt*4+nt][3] + ob1)*g1.y);
            *(float2*)(out + o0) = r0;
            *(float2*)(out + o1) = r1;
        }
    }
}

// ---------------------------------------------------------------------------
extern "C" void kernel_launch(void* const* d_in, const int* in_sizes, int n_in,
                              void* d_out, int out_size)
{
    const float* feat = (const float*)d_in[0];
    const float* nw   = (const float*)d_in[1];
    const float* nb   = (const float*)d_in[2];
    const float* onw  = (const float*)d_in[3];
    const float* onb  = (const float*)d_in[4];
    const float* aW   = (const float*)d_in[5];
    const float* ab   = (const float*)d_in[6];
    const float* agW  = (const float*)d_in[7];
    const float* agb  = (const float*)d_in[8];
    const float* oW   = (const float*)d_in[9];
    const float* ob   = (const float*)d_in[10];
    const float* gW   = (const float*)d_in[11];
    const float* gb   = (const float*)d_in[12];
    float* out = (float*)d_out;

    cudaFuncSetAttribute(k1_ln_proj_gate, cudaFuncAttributeMaxDynamicSharedMemorySize, K1_SMEM);
    cudaFuncSetAttribute(k2_einsum,       cudaFuncAttributeMaxDynamicSharedMemorySize, K2_SMEM);
    cudaFuncSetAttribute(k3_out,          cudaFuncAttributeMaxDynamicSharedMemorySize, K3_SMEM);

    k_pack<<<96, 256>>>(aW, agW, gW);
    k1_ln_proj_gate<<<LL/128, 512, K1_SMEM>>>(feat, nw, nb, ab, agb, gb);
    k2_einsum<<<dim3(21, 32), 512, K2_SMEM>>>();
    k3_out<<<dim3(6, 768), 256, K3_SMEM>>>(onw, onb, oW, ob, out);
}

// round 17
// speedup vs baseline: 1.3412x; 1.2052x over previous
#include <cuda_runtime.h>
#include <cuda_bf16.h>
#include <cuda_fp16.h>
#include <cstdint>

#define LDIM 768
#define LL   (768*768)
#define FDIM 128
#define PDIM 32

// ---------------- device scratch (allocation-free rule) ----------------
__device__ __nv_bfloat16 g_Wbh[192*128];            // reordered weights hi [n][k]
__device__ __nv_bfloat16 g_Wbl[192*128];            // reordered weights lo [n][k]
__device__ __nv_bfloat16 g_projh[(size_t)PDIM*LL];  // proj hi, channel-major [c][pos]
__device__ __nv_bfloat16 g_projl[(size_t)PDIM*LL];  // proj lo
__device__ float         g_pair[(size_t)PDIM*LL];   // pair, channel-major [c][i*L+j]
__device__ __half        g_gate16[(size_t)LL*FDIM]; // gate fp16 [pos][f]

// precise sigmoid (proj path: feeds LN-amplified einsum)
__device__ __forceinline__ float sigmoidf_(float x) { return 1.0f/(1.0f + __expf(-x)); }

__device__ __forceinline__ void ldsm4(uint32_t (&r)[4], uint32_t addr) {
    asm volatile("ldmatrix.sync.aligned.m8n8.x4.shared.b16 {%0,%1,%2,%3}, [%4];"
        : "=r"(r[0]), "=r"(r[1]), "=r"(r[2]), "=r"(r[3]) : "r"(addr));
}
__device__ __forceinline__ void mma_bf16(float (&c)[4], const uint32_t (&a)[4],
                                         uint32_t b0, uint32_t b1) {
    asm volatile("mma.sync.aligned.m16n8k16.row.col.f32.bf16.bf16.f32 "
        "{%0,%1,%2,%3},{%4,%5,%6,%7},{%8,%9},{%0,%1,%2,%3};"
        : "+f"(c[0]), "+f"(c[1]), "+f"(c[2]), "+f"(c[3])
        : "r"(a[0]), "r"(a[1]), "r"(a[2]), "r"(a[3]), "r"(b0), "r"(b1));
}
__device__ __forceinline__ uint32_t smaddr(const void* p) {
    return (uint32_t)__cvta_generic_to_shared(p);
}
__device__ __forceinline__ void cpasync16(uint32_t dst, const void* src) {
    asm volatile("cp.async.cg.shared.global [%0], [%1], 16;" :: "r"(dst), "l"(src));
}
#define CP_COMMIT()  asm volatile("cp.async.commit_group;")
#define CP_WAIT(n)   asm volatile("cp.async.wait_group %0;" :: "n"(n))

// packed fp16 sigmoid: sigma(z) = 0.5*tanh(z/2)+0.5, two lanes per MUFU
__device__ __forceinline__ __half2 sigmoid2_h2(__half2 z) {
    const __half2 h05 = __float2half2_rn(0.5f);
    __half2 zh = __hmul2(z, h05);
    uint32_t tt;
    asm("tanh.approx.f16x2 %0, %1;" : "=r"(tt) : "r"(*(uint32_t*)&zh));
    return __hfma2(*(__half2*)&tt, h05, h05);
}

// ---------------------------------------------------------------------------
// Kernel 0: pack weights -> bf16 hi/lo planes, [n][k] layout.
// ---------------------------------------------------------------------------
__global__ void k_pack(const float* __restrict__ aW, const float* __restrict__ agW,
                       const float* __restrict__ gW)
{
    int idx = blockIdx.x * 256 + threadIdx.x;
    if (idx >= 192*128) return;
    int n = idx >> 7, k = idx & 127;
    float v;
    if (n < 64) { int ch = n >> 1; v = (n & 1) ? agW[ch*FDIM + k] : aW[ch*FDIM + k]; }
    else        { v = gW[(n-64)*FDIM + k]; }
    __nv_bfloat16 vh = __float2bfloat16(v);
    __nv_bfloat16 vl = __float2bfloat16(v - __bfloat162float(vh));
    g_Wbh[idx] = vh;
    g_Wbl[idx] = vl;
}

// ---------------------------------------------------------------------------
// Kernel 1: LN(F) + X[128,128] @ Wcat[128,192] via bf16 tensor MMA.
// 512 threads = 16 warps; warp tile 32x48. SMSP-balanced mapping.
// LN now preloads all 8 feat rows (MLP=8) before the reduction loop.
// proj cols (<64): 3 terms + precise sigmoid; gate cols: 2 terms + f16x2 tanh.
// ---------------------------------------------------------------------------
#define X_STRIDE 136
#define K1_SMEM  174080

__global__ __launch_bounds__(512) void k1_ln_proj_gate(
    const float* __restrict__ feat,
    const float* __restrict__ nw, const float* __restrict__ nb,
    const float* __restrict__ ab, const float* __restrict__ agb,
    const float* __restrict__ gb)
{
    extern __shared__ char sm[];
    __nv_bfloat16* XH = (__nv_bfloat16*)sm;                 // 128*136*2 = 34816
    __nv_bfloat16* XL = (__nv_bfloat16*)(sm + 34816);
    __nv_bfloat16* WH = (__nv_bfloat16*)(sm + 69632);       // 192*136*2 = 52224
    __nv_bfloat16* WL = (__nv_bfloat16*)(sm + 121856);
    __half*        SGATE = (__half*)sm;                     // staging aliases
    __nv_bfloat16* SPH   = (__nv_bfloat16*)(sm + 32768);
    __nv_bfloat16* SPL   = (__nv_bfloat16*)(sm + 40960);

    int t = threadIdx.x, lane = t & 31, wid = t >> 5;
    int base = blockIdx.x * 128;

    // ---- async W prefetch (overlaps LN) ----
    uint32_t wh_b = smaddr(WH), wl_b = smaddr(WL);
    #pragma unroll
    for (int e = 0; e < 6; e++) {
        int idx = t + e*512;
        int n = idx >> 4, q = idx & 15;
        cpasync16(wh_b + (uint32_t)(n*272 + q*16), g_Wbh + n*128 + q*8);
        cpasync16(wl_b + (uint32_t)(n*272 + q*16), g_Wbl + n*128 + q*8);
    }
    CP_COMMIT();

    // ---- layernorm: preload 8 rows (MLP=8), then reduce/convert/store ----
    {
        float4 w4 = ((const float4*)nw)[lane];
        float4 b4 = ((const float4*)nb)[lane];
        float4 v[8];
        #pragma unroll
        for (int rr = 0; rr < 8; rr++)
            v[rr] = ((const float4*)(feat + (size_t)(base + wid*8 + rr)*FDIM))[lane];
        #pragma unroll
        for (int rr = 0; rr < 8; rr++) {
            int row = wid*8 + rr;
            float sum = v[rr].x+v[rr].y+v[rr].z+v[rr].w;
            float sq  = v[rr].x*v[rr].x + v[rr].y*v[rr].y
                      + v[rr].z*v[rr].z + v[rr].w*v[rr].w;
            #pragma unroll
            for (int o = 16; o > 0; o >>= 1) {
                sum += __shfl_xor_sync(0xffffffffu, sum, o);
                sq  += __shfl_xor_sync(0xffffffffu, sq,  o);
            }
            float mu   = sum * (1.0f/128.0f);
            float var  = sq  * (1.0f/128.0f) - mu*mu;
            float rstd = rsqrtf(var + 1e-5f);
            float x0 = (v[rr].x-mu)*rstd*w4.x + b4.x;
            float x1 = (v[rr].y-mu)*rstd*w4.y + b4.y;
            float x2 = (v[rr].z-mu)*rstd*w4.z + b4.z;
            float x3 = (v[rr].w-mu)*rstd*w4.w + b4.w;
            __nv_bfloat16 h0=__float2bfloat16(x0), h1=__float2bfloat16(x1),
                          h2=__float2bfloat16(x2), h3=__float2bfloat16(x3);
            __nv_bfloat16 l0=__float2bfloat16(x0-__bfloat162float(h0)),
                          l1=__float2bfloat16(x1-__bfloat162float(h1)),
                          l2=__float2bfloat16(x2-__bfloat162float(h2)),
                          l3=__float2bfloat16(x3-__bfloat162float(h3));
            __nv_bfloat162 hh0 = {h0,h1}, hh1 = {h2,h3};
            __nv_bfloat162 ll0 = {l0,l1}, ll1 = {l2,l3};
            uint2 hp, lp;
            hp.x = *(uint32_t*)&hh0; hp.y = *(uint32_t*)&hh1;
            lp.x = *(uint32_t*)&ll0; lp.y = *(uint32_t*)&ll1;
            *(uint2*)(XH + row*X_STRIDE + lane*4) = hp;
            *(uint2*)(XL + row*X_STRIDE + lane*4) = lp;
        }
    }
    CP_WAIT(0);
    __syncthreads();

    // SMSP-balanced: warpM = SMSP index, warpN varies within each SMSP
    int warpM = wid & 3;
    int warpN = wid >> 2;
    float c[12][4];
    #pragma unroll
    for (int i = 0; i < 12; i++) { c[i][0]=0.f; c[i][1]=0.f; c[i][2]=0.f; c[i][3]=0.f; }

    int grp = lane >> 3, lr = lane & 7;
    int a_row = (grp & 1)*8 + lr, a_k = (grp >> 1)*8;
    int b_row = (grp >> 1)*8 + lr, b_k = (grp & 1)*8;

    uint32_t xh_b = smaddr(XH), xl_b = smaddr(XL);

    for (int kb = 0; kb < 8; kb++) {
        uint32_t ah[2][4], al[2][4], bh[3][4], bl[3][4];
        #pragma unroll
        for (int mt = 0; mt < 2; mt++) {
            uint32_t off = (uint32_t)(((warpM*32 + mt*16 + a_row)*X_STRIDE + kb*16 + a_k)*2);
            ldsm4(ah[mt], xh_b + off);
            ldsm4(al[mt], xl_b + off);
        }
        #pragma unroll
        for (int np = 0; np < 3; np++) {
            uint32_t off = (uint32_t)(((warpN*48 + np*16 + b_row)*X_STRIDE + kb*16 + b_k)*2);
            ldsm4(bh[np], wh_b + off);
            ldsm4(bl[np], wl_b + off);
        }
        #pragma unroll
        for (int mt = 0; mt < 2; mt++)
            #pragma unroll
            for (int nt = 0; nt < 6; nt++) {
                int np = nt >> 1, h = (nt & 1)*2;
                mma_bf16(c[mt*6+nt], ah[mt], bh[np][h], bh[np][h+1]);   // hi*hi
                mma_bf16(c[mt*6+nt], ah[mt], bl[np][h], bl[np][h+1]);   // hi*lo
                if (warpN*48 + nt*8 < 64)
                    mma_bf16(c[mt*6+nt], al[mt], bh[np][h], bh[np][h+1]); // lo*hi (proj only)
            }
    }
    __syncthreads();

    int r0b = warpM*32 + (lane >> 2);
    int cq  = lane & 3;
    #pragma unroll
    for (int mt = 0; mt < 2; mt++) {
        int r0 = r0b + mt*16, r1 = r0 + 8;
        #pragma unroll
        for (int nt = 0; nt < 6; nt++) {
            int nb_ = warpN*48 + nt*8;
            float v0 = c[mt*6+nt][0], v1 = c[mt*6+nt][1];
            float v2 = c[mt*6+nt][2], v3 = c[mt*6+nt][3];
            if (nb_ < 64) {
                int ch = (nb_ >> 1) + cq;
                float abv = ab[ch], agbv = agb[ch];
                float p0 = (v0 + abv) * sigmoidf_(v1 + agbv);
                float p1 = (v2 + abv) * sigmoidf_(v3 + agbv);
                __nv_bfloat16 h0 = __float2bfloat16(p0);
                __nv_bfloat16 h1 = __float2bfloat16(p1);
                SPH[ch*128 + r0] = h0;
                SPH[ch*128 + r1] = h1;
                SPL[ch*128 + r0] = __float2bfloat16(p0 - __bfloat162float(h0));
                SPL[ch*128 + r1] = __float2bfloat16(p1 - __bfloat162float(h1));
            } else {
                int f = nb_ - 64 + 2*cq;
                float zb0 = gb[f], zb1 = gb[f+1];
                __half2 z01 = __floats2half2_rn(v0 + zb0, v1 + zb1);
                __half2 z23 = __floats2half2_rn(v2 + zb0, v3 + zb1);
                *(__half2*)(SGATE + r0*128 + f) = sigmoid2_h2(z01);
                *(__half2*)(SGATE + r1*128 + f) = sigmoid2_h2(z23);
            }
        }
    }
    __syncthreads();

    {
        const float4* sg = (const float4*)SGATE;
        float4* dg = (float4*)(g_gate16 + (size_t)base*FDIM);
        for (int i = t; i < 2048; i += 512) dg[i] = sg[i];
        const float4* sph = (const float4*)SPH;
        const float4* spl = (const float4*)SPL;
        for (int i = t; i < 512; i += 512) {
            int ch = i >> 4, q = i & 15;
            ((float4*)(g_projh + (size_t)ch*LL + base))[q] = sph[i];
            ((float4*)(g_projl + (size_t)ch*LL + base))[q] = spl[i];
        }
    }
}

// ---------------------------------------------------------------------------
// Kernel 2: per-channel SYRK pair = proj proj^T via bf16x3 tensor MMA.
// (R12/R16 version: diag tiles alias B->A, cp.async double-buffer, K-chunk 64)
// ---------------------------------------------------------------------------
#define K2STRIDE 72
#define K2PLANE  18432
#define K2STAGE  73728
#define K2_SMEM  147456

__global__ __launch_bounds__(512) void k2_einsum()
{
    extern __shared__ char sm[];
    uint32_t sbase = smaddr(sm);

    int t = threadIdx.x, lane = t & 31, wid = t >> 5;
    int warpM = wid >> 2, warpN = wid & 3;
    int ch = blockIdx.y;

    int tt = blockIdx.x, bi = 0;
    while (tt >= 6 - bi) { tt -= 6 - bi; bi++; }
    int bj = bi + tt;
    int i0 = bi*128, j0 = bj*128;
    bool diag = (bi == bj);

    const __nv_bfloat16* Ph = g_projh + (size_t)ch*LL;
    const __nv_bfloat16* Pl = g_projl + (size_t)ch*LL;
    const __nv_bfloat16* psrc[4];
    int rowbase[4];
    psrc[0] = Ph; rowbase[0] = i0;
    psrc[1] = Pl; rowbase[1] = i0;
    psrc[2] = Ph; rowbase[2] = j0;
    psrc[3] = Pl; rowbase[3] = j0;

    auto load_chunk = [&](int c, int s) {
        int k0 = c*64;
        uint32_t dst0 = sbase + s*K2STAGE;
        #pragma unroll
        for (int e = 0; e < 8; e++) {
            if (diag && e >= 4) continue;
            int idx = t + e*512;
            int plane = idx >> 10;
            int r = (idx >> 3) & 127;
            int q = idx & 7;
            cpasync16(dst0 + (uint32_t)(plane*K2PLANE + r*144 + q*16),
                      psrc[plane] + (size_t)(rowbase[plane] + r)*LDIM + k0 + q*8);
        }
        CP_COMMIT();
    };

    float c[8][4];
    #pragma unroll
    for (int i = 0; i < 8; i++) { c[i][0]=0.f; c[i][1]=0.f; c[i][2]=0.f; c[i][3]=0.f; }

    int grp = lane >> 3, lr = lane & 7;
    int a_row = (grp & 1)*8 + lr, a_k = (grp >> 1)*8;
    int b_row = (grp >> 1)*8 + lr, b_k = (grp & 1)*8;

    load_chunk(0, 0);
    load_chunk(1, 1);

    for (int cidx = 0; cidx < 12; cidx++) {
        if (cidx < 11) { CP_WAIT(1); } else { CP_WAIT(0); }
        __syncthreads();

        int s = cidx & 1;
        uint32_t ah_b = sbase + s*K2STAGE;
        uint32_t al_b = ah_b + K2PLANE;
        uint32_t bh_b = diag ? ah_b : (ah_b + 2*K2PLANE);
        uint32_t bl_b = diag ? al_b : (ah_b + 3*K2PLANE);

        #pragma unroll
        for (int kb = 0; kb < 4; kb++) {
            uint32_t ah[2][4], al[2][4], bh[2][4], bl[2][4];
            #pragma unroll
            for (int mt = 0; mt < 2; mt++) {
                uint32_t off = (uint32_t)(((warpM*32 + mt*16 + a_row)*K2STRIDE + kb*16 + a_k)*2);
                ldsm4(ah[mt], ah_b + off);
                ldsm4(al[mt], al_b + off);
            }
            #pragma unroll
            for (int np = 0; np < 2; np++) {
                uint32_t off = (uint32_t)(((warpN*32 + np*16 + b_row)*K2STRIDE + kb*16 + b_k)*2);
                ldsm4(bh[np], bh_b + off);
                ldsm4(bl[np], bl_b + off);
            }
            #pragma unroll
            for (int mt = 0; mt < 2; mt++)
                #pragma unroll
                for (int nt = 0; nt < 4; nt++) {
                    int np = nt >> 1, h = (nt & 1)*2;
                    mma_bf16(c[mt*4+nt], ah[mt], bh[np][h], bh[np][h+1]);
                    mma_bf16(c[mt*4+nt], ah[mt], bl[np][h], bl[np][h+1]);
                    mma_bf16(c[mt*4+nt], al[mt], bh[np][h], bh[np][h+1]);
                }
        }
        __syncthreads();
        if (cidx + 2 < 12) load_chunk(cidx + 2, s);
    }

    float* Cc = g_pair + (size_t)ch*LL;
    #pragma unroll
    for (int mt = 0; mt < 2; mt++) {
        int r = i0 + warpM*32 + mt*16 + (lane >> 2);
        #pragma unroll
        for (int nt = 0; nt < 4; nt++) {
            int col = j0 + warpN*32 + nt*8 + 2*(lane & 3);
            float2 v01 = make_float2(c[mt*4+nt][0], c[mt*4+nt][1]);
            float2 v23 = make_float2(c[mt*4+nt][2], c[mt*4+nt][3]);
            *(float2*)(Cc + (size_t)r*LDIM + col)     = v01;
            *(float2*)(Cc + (size_t)(r+8)*LDIM + col) = v23;
            if (!diag) {
                Cc[(size_t)col*LDIM     + r]   = v01.x;
                Cc[(size_t)(col+1)*LDIM + r]   = v01.y;
                Cc[(size_t)col*LDIM     + r+8] = v23.x;
                Cc[(size_t)(col+1)*LDIM + r+8] = v23.y;
            }
        }
    }
}

// ---------------------------------------------------------------------------
// Kernel 3: out = (LN_P(pair) @ oW^T + ob) * gate. 256 threads / 128 positions.
// cp.async gate prefetch (GT_STRIDE=136, 16B-aligned rows). R16 version.
// ---------------------------------------------------------------------------
#define A_STRIDE 40
#define GT_STRIDE 136
#define K3_SMEM  75776

__global__ __launch_bounds__(256) void k3_out(
    const float* __restrict__ onw, const float* __restrict__ onb,
    const float* __restrict__ oW, const float* __restrict__ ob,
    float* __restrict__ out)
{
    extern __shared__ char sm[];
    __nv_bfloat16* AH = (__nv_bfloat16*)sm;
    __nv_bfloat16* AL = (__nv_bfloat16*)(sm + 10240);
    __nv_bfloat16* BH = (__nv_bfloat16*)(sm + 20480);
    __nv_bfloat16* BL = (__nv_bfloat16*)(sm + 30720);
    __half*        GT = (__half*)(sm + 40960);   // [128][GT_STRIDE]

    int t = threadIdx.x, lane = t & 31, wid = t >> 5;
    int i  = blockIdx.y;
    int j0 = blockIdx.x * 128;
    size_t posbase = (size_t)i*LDIM + j0;

    // ---- async gate prefetch ----
    {
        uint32_t gt_b = smaddr(GT);
        #pragma unroll
        for (int e = 0; e < 8; e++) {
            int idx = t + e*256;
            int row = idx >> 4, q = idx & 15;
            cpasync16(gt_b + (uint32_t)((row*GT_STRIDE + q*8)*2),
                      g_gate16 + (posbase + row)*FDIM + q*8);
        }
        CP_COMMIT();
    }

    if (t < 128) {
        int jj = t;
        float y[32];
        float sum = 0.f, sq = 0.f;
        #pragma unroll
        for (int cc = 0; cc < 32; cc++) {
            y[cc] = g_pair[(size_t)cc*LL + posbase + jj];
            sum += y[cc];
            sq  += y[cc]*y[cc];
        }
        float mu   = sum * (1.0f/32.0f);
        float var  = sq  * (1.0f/32.0f) - mu*mu;
        float rstd = rsqrtf(var + 1e-5f);
        #pragma unroll
        for (int q = 0; q < 16; q++) {
            float v0 = (y[2*q]  -mu)*rstd*onw[2*q]   + onb[2*q];
            float v1 = (y[2*q+1]-mu)*rstd*onw[2*q+1] + onb[2*q+1];
            __nv_bfloat16 h0 = __float2bfloat16(v0);
            __nv_bfloat16 h1 = __float2bfloat16(v1);
            __nv_bfloat162 hh = {h0, h1};
            __nv_bfloat162 ll = {__float2bfloat16(v0 - __bfloat162float(h0)),
                                 __float2bfloat16(v1 - __bfloat162float(h1))};
            *(uint32_t*)(AH + jj*A_STRIDE + 2*q) = *(uint32_t*)&hh;
            *(uint32_t*)(AL + jj*A_STRIDE + 2*q) = *(uint32_t*)&ll;
        }
    } else {
        int t2 = t - 128;
        #pragma unroll
        for (int e = 0; e < 32; e++) {
            int idx = t2 + e*128;
            int f = idx >> 5, c2 = idx & 31;
            float w = oW[idx];
            __nv_bfloat16 wh = __float2bfloat16(w);
            BH[f*A_STRIDE + c2] = wh;
            BL[f*A_STRIDE + c2] = __float2bfloat16(w - __bfloat162float(wh));
        }
    }
    __syncthreads();

    int warpM = wid >> 2, warpN = wid & 3;
    float c[16][4];
    #pragma unroll
    for (int q = 0; q < 16; q++) { c[q][0]=0.f; c[q][1]=0.f; c[q][2]=0.f; c[q][3]=0.f; }

    int grp = lane >> 3, lr = lane & 7;
    int a_row = (grp & 1)*8 + lr, a_k = (grp >> 1)*8;
    int b_row = (grp >> 1)*8 + lr, b_k = (grp & 1)*8;

    uint32_t ah_b = smaddr(AH), al_b = smaddr(AL);
    uint32_t bh_b = smaddr(BH), bl_b = smaddr(BL);

    #pragma unroll
    for (int kb = 0; kb < 2; kb++) {
        uint32_t ah[4][4], al[4][4], bh[2][4], bl[2][4];
        #pragma unroll
        for (int mt = 0; mt < 4; mt++) {
            uint32_t off = (uint32_t)(((warpM*64 + mt*16 + a_row)*A_STRIDE + kb*16 + a_k)*2);
            ldsm4(ah[mt], ah_b + off);
            ldsm4(al[mt], al_b + off);
        }
        #pragma unroll
        for (int np = 0; np < 2; np++) {
            uint32_t off = (uint32_t)(((warpN*32 + np*16 + b_row)*A_STRIDE + kb*16 + b_k)*2);
            ldsm4(bh[np], bh_b + off);
            ldsm4(bl[np], bl_b + off);
        }
        #pragma unroll
        for (int mt = 0; mt < 4; mt++)
            #pragma unroll
            for (int nt = 0; nt < 4; nt++) {
                int np = nt >> 1, h = (nt & 1)*2;
                mma_bf16(c[mt*4+nt], ah[mt], bh[np][h], bh[np][h+1]);
                mma_bf16(c[mt*4+nt], ah[mt], bl[np][h], bl[np][h+1]);
                mma_bf16(c[mt*4+nt], al[mt], bh[np][h], bh[np][h+1]);
            }
    }

    CP_WAIT(0);
    __syncthreads();

    #pragma unroll
    for (int mt = 0; mt < 4; mt++) {
        int r = warpM*64 + mt*16 + (lane >> 2);
        #pragma unroll
        for (int nt = 0; nt < 4; nt++) {
            int col = warpN*32 + nt*8 + 2*(lane & 3);
            float ob0 = ob[col], ob1 = ob[col+1];
            size_t o0 = (posbase + r)*FDIM + col;
            size_t o1 = o0 + (size_t)8*FDIM;
            __half2 gh0 = *(const __half2*)(GT + r*GT_STRIDE + col);
            __half2 gh1 = *(const __half2*)(GT + (r+8)*GT_STRIDE + col);
            float2 g0 = __half22float2(gh0);
            float2 g1 = __half22float2(gh1);
            float2 r0 = make_float2((c[mt*4+nt][0] + ob0)*g0.x, (c[mt*4+nt][1] + ob1)*g0.y);
            float2 r1 = make_float2((c[mt*4+nt][2] + ob0)*g1.x, (c[mt*4+nt][3] + ob1)*g1.y);
            *(float2*)(out + o0) = r0;
            *(float2*)(out + o1) = r1;
        }
    }
}

// ---------------------------------------------------------------------------
extern "C" void kernel_launch(void* const* d_in, const int* in_sizes, int n_in,
                              void* d_out, int out_size)
{
    const float* feat = (const float*)d_in[0];
    const float* nw   = (const float*)d_in[1];
    const float* nb   = (const float*)d_in[2];
    const float* onw  = (const float*)d_in[3];
    const float* onb  = (const float*)d_in[4];
    const float* aW   = (const float*)d_in[5];
    const float* ab   = (const float*)d_in[6];
    const float* agW  = (const float*)d_in[7];
    const float* agb  = (const float*)d_in[8];
    const float* oW   = (const float*)d_in[9];
    const float* ob   = (const float*)d_in[10];
    const float* gW   = (const float*)d_in[11];
    const float* gb   = (const float*)d_in[12];
    float* out = (float*)d_out;

    cudaFuncSetAttribute(k1_ln_proj_gate, cudaFuncAttributeMaxDynamicSharedMemorySize, K1_SMEM);
    cudaFuncSetAttribute(k2_einsum,       cudaFuncAttributeMaxDynamicSharedMemorySize, K2_SMEM);
    cudaFuncSetAttribute(k3_out,          cudaFuncAttributeMaxDynamicSharedMemorySize, K3_SMEM);

    k_pack<<<96, 256>>>(aW, agW, gW);
    k1_ln_proj_gate<<<LL/128, 512, K1_SMEM>>>(feat, nw, nb, ab, agb, gb);
    k2_einsum<<<dim3(21, 32), 512, K2_SMEM>>>();
    k3_out<<<dim3(6, 768), 256, K3_SMEM>>>(onw, onb, oW, ob, out);
}